// round 6
// baseline (speedup 1.0000x reference)
#include <cuda_runtime.h>
#include <math.h>

#define NP 100000
#define ND 20000
#define DD 128
#define EP 1600000
#define ED 800000
#define LN_EPS 1e-5f
#define XP64 68   // sX row stride for 64-row tiles: mult of 4 (16B-aligned), 4-bank skew

// ---------------- scratch (static device globals; no runtime allocation) ----
__device__ float g_xw  [(size_t)NP * DD];  // dinv[r] * (x_prot @ W_gcn)   (premultiplied)
__device__ float g_acc [(size_t)NP * DD];  // everything accumulates here
__device__ float g_yd  [(size_t)ND * DD];  // x_drug @ W_td + b_td
__device__ float g_deg [NP];
__device__ float g_dinv[NP];
__device__ float g_cnt [NP];
__device__ float g_rcnt[NP];

// ---------------- f32x2 packed math -----------------------------------------
__device__ __forceinline__ void fma2(unsigned long long& d, unsigned long long a,
                                     unsigned long long b) {
    asm("fma.rn.f32x2 %0, %1, %2, %0;" : "+l"(d) : "l"(a), "l"(b));
}
__device__ __forceinline__ unsigned long long splat2(float x) {
    unsigned long long r;
    asm("mov.b64 %0, {%1, %1};" : "=l"(r) : "r"(__float_as_uint(x)));
    return r;
}
__device__ __forceinline__ float2 unpack2(unsigned long long v) {
    float2 f;
    asm("mov.b64 {%0, %1}, %2;" : "=f"(f.x), "=f"(f.y) : "l"(v));
    return f;
}

// ---------------- atomic helper ---------------------------------------------
__device__ __forceinline__ void red_add_v4(float* p, float4 v) {
#if defined(__CUDA_ARCH__) && (__CUDA_ARCH__ >= 900)
    atomicAdd(reinterpret_cast<float4*>(p), v);
#else
    atomicAdd(p + 0, v.x); atomicAdd(p + 1, v.y);
    atomicAdd(p + 2, v.z); atomicAdd(p + 3, v.w);
#endif
}

// ---------------- init: deg=1 (self loop), cnt=0 ----------------------------
__global__ void k_init() {
    int i = blockIdx.x * blockDim.x + threadIdx.x;
    if (i < NP) { g_deg[i] = 1.f; g_cnt[i] = 0.f; }
}

// ---------------- degree + dti count (fused, grid-stride) -------------------
__global__ void k_deg(const int* __restrict__ col, const int* __restrict__ dp) {
    const int stride = gridDim.x * blockDim.x;
    for (int e = blockIdx.x * blockDim.x + threadIdx.x; e < EP + ED; e += stride) {
        if (e < EP) atomicAdd(&g_deg[__ldg(col + e)], 1.f);
        else        atomicAdd(&g_cnt[__ldg(dp + (e - EP))], 1.f);
    }
}

__global__ void k_dinv() {
    int i = blockIdx.x * blockDim.x + threadIdx.x;
    if (i < NP) {
        g_dinv[i] = rsqrtf(g_deg[i]);            // deg >= 1 always
        g_rcnt[i] = 1.f / fmaxf(g_cnt[i], 1.f);
    }
}

// ---------------- fused protein GEMMs (FFMA2, 64-row tile, 4x8 micro) -------
// 2 CTAs/SM: smem = sX(64x128 transposed, 34.8KB) + W chunks (2x16KB) = 66.8KB,
// regs capped at 128 via __launch_bounds__(256,2). W streamed in 4 chunks of 32 k.
// g_xw  = dinv[r] * (x @ W_gcn)          (premultiplied for the edge scatter)
// g_acc = x @ W_pr + b_pr + b_gcn + 1e-6 + dinv[r] * g_xw[r]   (self loop)
__global__ __launch_bounds__(256, 2) void k_gemm_prot(
    const float* __restrict__ x,
    const float* __restrict__ Wg, const float* __restrict__ Wp,
    const float* __restrict__ bg, const float* __restrict__ bp)
{
    extern __shared__ float sm[];
    float* sX  = sm;                       // DD * XP64 = 8704 floats (k-major)
    float* sWg = sm + DD * XP64;           // 32 * 128 chunk
    float* sWp = sWg + 32 * DD;            // 32 * 128 chunk
    const int tid  = threadIdx.x;
    const int row0 = blockIdx.x * 64;

    // load A tile (64 rows x 128 k), transposed to k-major
    for (int idx = tid; idx < 64 * DD; idx += 256) {
        int r = idx >> 7, c = idx & 127;
        int gr = row0 + r;
        sX[c * XP64 + r] = (gr < NP) ? __ldg(x + (size_t)gr * DD + c) : 0.f;
    }

    const int c0 = (tid & 15) * 8;
    const int r0 = (tid >> 4) * 4;
    unsigned long long aG[4][4], aP[4][4];
#pragma unroll
    for (int i = 0; i < 4; i++)
#pragma unroll
        for (int j = 0; j < 4; j++) { aG[i][j] = 0ull; aP[i][j] = 0ull; }

    for (int p = 0; p < 4; p++) {
        __syncthreads();
        // stage W chunk rows [p*32, p*32+32)
        for (int idx = tid; idx < 32 * DD / 4; idx += 256) {
            reinterpret_cast<float4*>(sWg)[idx] =
                __ldg(reinterpret_cast<const float4*>(Wg) + p * (32 * DD / 4) + idx);
            reinterpret_cast<float4*>(sWp)[idx] =
                __ldg(reinterpret_cast<const float4*>(Wp) + p * (32 * DD / 4) + idx);
        }
        __syncthreads();

#pragma unroll 4
        for (int kk = 0; kk < 32; kk++) {
            int k = p * 32 + kk;
            float4 a = *reinterpret_cast<const float4*>(sX + k * XP64 + r0);
            ulonglong2 bg0 = *reinterpret_cast<const ulonglong2*>(sWg + kk * DD + c0);
            ulonglong2 bg1 = *reinterpret_cast<const ulonglong2*>(sWg + kk * DD + c0 + 4);
            ulonglong2 bp0 = *reinterpret_cast<const ulonglong2*>(sWp + kk * DD + c0);
            ulonglong2 bp1 = *reinterpret_cast<const ulonglong2*>(sWp + kk * DD + c0 + 4);
            float ar[4] = {a.x, a.y, a.z, a.w};
#pragma unroll
            for (int i = 0; i < 4; i++) {
                unsigned long long a2 = splat2(ar[i]);
                fma2(aG[i][0], a2, bg0.x); fma2(aG[i][1], a2, bg0.y);
                fma2(aG[i][2], a2, bg1.x); fma2(aG[i][3], a2, bg1.y);
                fma2(aP[i][0], a2, bp0.x); fma2(aP[i][1], a2, bp0.y);
                fma2(aP[i][2], a2, bp1.x); fma2(aP[i][3], a2, bp1.y);
            }
        }
    }

    float4 bgA = __ldg(reinterpret_cast<const float4*>(bg + c0));
    float4 bgB = __ldg(reinterpret_cast<const float4*>(bg + c0 + 4));
    float4 bpA = __ldg(reinterpret_cast<const float4*>(bp + c0));
    float4 bpB = __ldg(reinterpret_cast<const float4*>(bp + c0 + 4));
    float bias[8] = {bgA.x + bpA.x + 1e-6f, bgA.y + bpA.y + 1e-6f,
                     bgA.z + bpA.z + 1e-6f, bgA.w + bpA.w + 1e-6f,
                     bgB.x + bpB.x + 1e-6f, bgB.y + bpB.y + 1e-6f,
                     bgB.z + bpB.z + 1e-6f, bgB.w + bpB.w + 1e-6f};
#pragma unroll
    for (int i = 0; i < 4; i++) {
        int gr = row0 + r0 + i;
        if (gr < NP) {
            float di = g_dinv[gr];
            float xs[8], oa[8];
#pragma unroll
            for (int j = 0; j < 4; j++) {
                float2 fg = unpack2(aG[i][j]);
                float2 fp = unpack2(aP[i][j]);
                xs[2*j]   = di * fg.x;        // premultiplied by dinv[row]
                xs[2*j+1] = di * fg.y;
                oa[2*j]   = fp.x + bias[2*j]   + di * xs[2*j];   // = di^2 * xw
                oa[2*j+1] = fp.y + bias[2*j+1] + di * xs[2*j+1];
            }
            float* pw = g_xw  + (size_t)gr * DD + c0;
            float* pa = g_acc + (size_t)gr * DD + c0;
            *reinterpret_cast<float4*>(pw)     = make_float4(xs[0], xs[1], xs[2], xs[3]);
            *reinterpret_cast<float4*>(pw + 4) = make_float4(xs[4], xs[5], xs[6], xs[7]);
            *reinterpret_cast<float4*>(pa)     = make_float4(oa[0], oa[1], oa[2], oa[3]);
            *reinterpret_cast<float4*>(pa + 4) = make_float4(oa[4], oa[5], oa[6], oa[7]);
        }
    }
}

// ---------------- drug GEMM (FFMA2, 64-row tile, 4x8 micro, full W) ---------
// smem = 64KB (W) + 34.8KB (sX) = 98.9KB -> 2 CTAs/SM; regs ~70.
__global__ __launch_bounds__(256, 2) void k_gemm_drug(
    const float* __restrict__ x, const float* __restrict__ W,
    const float* __restrict__ b)
{
    extern __shared__ float sm[];
    float* sW = sm;                    // 128*128
    float* sX = sm + DD * DD;          // DD * XP64
    const int tid  = threadIdx.x;
    const int row0 = blockIdx.x * 64;

    for (int idx = tid; idx < DD * DD / 4; idx += 256)
        reinterpret_cast<float4*>(sW)[idx] = __ldg(reinterpret_cast<const float4*>(W) + idx);
    for (int idx = tid; idx < 64 * DD; idx += 256) {
        int r = idx >> 7, c = idx & 127;
        int gr = row0 + r;
        sX[c * XP64 + r] = (gr < ND) ? __ldg(x + (size_t)gr * DD + c) : 0.f;
    }
    __syncthreads();

    const int c0 = (tid & 15) * 8;
    const int r0 = (tid >> 4) * 4;
    unsigned long long acc[4][4];
#pragma unroll
    for (int i = 0; i < 4; i++)
#pragma unroll
        for (int j = 0; j < 4; j++) acc[i][j] = 0ull;

#pragma unroll 4
    for (int k = 0; k < DD; k++) {
        float4 a = *reinterpret_cast<const float4*>(sX + k * XP64 + r0);
        ulonglong2 b0 = *reinterpret_cast<const ulonglong2*>(sW + k * DD + c0);
        ulonglong2 b1 = *reinterpret_cast<const ulonglong2*>(sW + k * DD + c0 + 4);
        float ar[4] = {a.x, a.y, a.z, a.w};
#pragma unroll
        for (int i = 0; i < 4; i++) {
            unsigned long long a2 = splat2(ar[i]);
            fma2(acc[i][0], a2, b0.x); fma2(acc[i][1], a2, b0.y);
            fma2(acc[i][2], a2, b1.x); fma2(acc[i][3], a2, b1.y);
        }
    }

    float4 bA = __ldg(reinterpret_cast<const float4*>(b + c0));
    float4 bB = __ldg(reinterpret_cast<const float4*>(b + c0 + 4));
    float bias[8] = {bA.x, bA.y, bA.z, bA.w, bB.x, bB.y, bB.z, bB.w};
#pragma unroll
    for (int i = 0; i < 4; i++) {
        int gr = row0 + r0 + i;
        if (gr < ND) {
            float o[8];
#pragma unroll
            for (int j = 0; j < 4; j++) {
                float2 f = unpack2(acc[i][j]);
                o[2*j] = f.x + bias[2*j]; o[2*j+1] = f.y + bias[2*j+1];
            }
            float* py = g_yd + (size_t)gr * DD + c0;
            *reinterpret_cast<float4*>(py)     = make_float4(o[0], o[1], o[2], o[3]);
            *reinterpret_cast<float4*>(py + 4) = make_float4(o[4], o[5], o[6], o[7]);
        }
    }
}

// ---------------- PPI edge scatter: one warp per edge -----------------------
// g_xw already premultiplied by dinv[row]; only dinv[col] needed here.
__global__ void k_ppi(const int* __restrict__ ei) {
    size_t t = (size_t)blockIdx.x * blockDim.x + threadIdx.x;
    int e = (int)(t >> 5);
    if (e >= EP) return;
    int lane = (int)(t & 31);
    int row = __ldg(ei + e);
    int col = __ldg(ei + EP + e);
    float nrm = g_dinv[col];
    float4 v = *reinterpret_cast<const float4*>(g_xw + (size_t)row * DD + lane * 4);
    v.x *= nrm; v.y *= nrm; v.z *= nrm; v.w *= nrm;
    red_add_v4(g_acc + (size_t)col * DD + lane * 4, v);
}

// ---------------- DTI edge scatter: pre-scaled by 1/cnt, into g_acc ---------
__global__ void k_dti(const int* __restrict__ dd, const int* __restrict__ dp) {
    size_t t = (size_t)blockIdx.x * blockDim.x + threadIdx.x;
    int e = (int)(t >> 5);
    if (e >= ED) return;
    int lane = (int)(t & 31);
    int drug = __ldg(dd + e);
    int prot = __ldg(dp + e);
    float rc = g_rcnt[prot];
    float4 v = *reinterpret_cast<const float4*>(g_yd + (size_t)drug * DD + lane * 4);
    v.x *= rc; v.y *= rc; v.z *= rc; v.w *= rc;
    red_add_v4(g_acc + (size_t)prot * DD + lane * 4, v);
}

// ---------------- finalize: y = LN(g_acc), warp per row ---------------------
__global__ void k_fin(float* __restrict__ out) {
    size_t t = (size_t)blockIdx.x * blockDim.x + threadIdx.x;
    int r = (int)(t >> 5);
    if (r >= NP) return;
    int lane = (int)(t & 31);
    float4 v = *reinterpret_cast<const float4*>(g_acc + (size_t)r * DD + lane * 4);
    float sum = v.x + v.y + v.z + v.w;
#pragma unroll
    for (int off = 16; off > 0; off >>= 1)
        sum += __shfl_xor_sync(0xFFFFFFFFu, sum, off);
    float mu = sum * (1.f / DD);
    float4 d = make_float4(v.x - mu, v.y - mu, v.z - mu, v.w - mu);
    float ss = d.x * d.x + d.y * d.y + d.z * d.z + d.w * d.w;
#pragma unroll
    for (int off = 16; off > 0; off >>= 1)
        ss += __shfl_xor_sync(0xFFFFFFFFu, ss, off);
    float inv = rsqrtf(ss * (1.f / DD) + LN_EPS);
    float4 o = make_float4(d.x * inv, d.y * inv, d.z * inv, d.w * inv);
    *reinterpret_cast<float4*>(out + (size_t)r * DD + lane * 4) = o;
}

// ---------------- launch ----------------------------------------------------
extern "C" void kernel_launch(void* const* d_in, const int* in_sizes, int n_in,
                              void* d_out, int out_size) {
    const float* x_prot = (const float*)d_in[0];
    const float* x_drug = (const float*)d_in[1];
    const float* W_gcn  = (const float*)d_in[2];
    const float* b_gcn  = (const float*)d_in[3];
    const float* W_td   = (const float*)d_in[4];
    const float* b_td   = (const float*)d_in[5];
    const float* W_pr   = (const float*)d_in[6];
    const float* b_pr   = (const float*)d_in[7];
    const int*   ppi    = (const int*)d_in[8];   // [2, EP] flattened
    const int*   dti_d  = (const int*)d_in[9];
    const int*   dti_p  = (const int*)d_in[10];
    float* out = (float*)d_out;

    const int SMEM_PROT = (DD * XP64 + 2 * 32 * DD) * 4;  // 67584 B
    const int SMEM_DRUG = (DD * DD + DD * XP64) * 4;      // 100352 B
    cudaFuncSetAttribute(k_gemm_prot, cudaFuncAttributeMaxDynamicSharedMemorySize, SMEM_PROT);
    cudaFuncSetAttribute(k_gemm_drug, cudaFuncAttributeMaxDynamicSharedMemorySize, SMEM_DRUG);

    // 1. init (deg=1, cnt=0)
    k_init<<<(NP + 255) / 256, 256>>>();
    // 2. degree + dti counts (fused grid-stride)
    k_deg<<<1184, 256>>>(ppi + EP, dti_p);
    // 3. dinv + rcnt
    k_dinv<<<(NP + 255) / 256, 256>>>();
    // 4. fused protein GEMMs  (profiled slot)
    k_gemm_prot<<<(NP + 63) / 64, 256, SMEM_PROT>>>(x_prot, W_gcn, W_pr, b_gcn, b_pr);
    // 5. PPI scatter (warp per edge)
    k_ppi<<<(int)(((size_t)EP * 32 + 255) / 256), 256>>>(ppi);
    // 6. drug GEMM
    k_gemm_drug<<<(ND + 63) / 64, 256, SMEM_DRUG>>>(x_drug, W_td, b_td);
    // 7. DTI scatter (pre-scaled mean, into g_acc)
    k_dti<<<(int)(((size_t)ED * 32 + 255) / 256), 256>>>(dti_d, dti_p);
    // 8. finalize + layernorm
    k_fin<<<(int)(((size_t)NP * 32 + 255) / 256), 256>>>(out);
}

// round 12
// speedup vs baseline: 1.4241x; 1.4241x over previous
#include <cuda_runtime.h>
#include <math.h>

#define NP 100000
#define ND 20000
#define DD 128
#define EP 1600000
#define ED 800000
#define LN_EPS 1e-5f
#define XPAD 132     // sX row stride: multiple of 4 (16B-aligned float4 rows)
#define CAP_P 96     // per-node PPI bucket capacity (in-deg ~ Poisson(16))
#define CAP_D 48     // per-node DTI bucket capacity (in-deg ~ Poisson(8))

// ---------------- scratch (static device globals; no runtime allocation) ----
__device__ float g_xw  [(size_t)NP * DD];  // dinv[r] * (x_prot @ W_gcn)  (premultiplied)
__device__ float g_acc [(size_t)NP * DD];  // x@Wpr + biases + 1e-6 + selfloop
__device__ float g_yd  [(size_t)ND * DD];  // x_drug @ W_td + b_td
__device__ float g_dinv[NP];
__device__ float g_rcnt[NP];
__device__ int   c_ppi [NP];               // PPI in-degree (excl self loop)
__device__ int   c_dti [NP];               // DTI count per protein
__device__ int   bin_ppi[(size_t)NP * CAP_P];  // src protein ids grouped by target
__device__ int   bin_dti[(size_t)NP * CAP_D];  // drug ids grouped by protein

// ---------------- f32x2 packed math -----------------------------------------
__device__ __forceinline__ void fma2(unsigned long long& d, unsigned long long a,
                                     unsigned long long b) {
    asm("fma.rn.f32x2 %0, %1, %2, %0;" : "+l"(d) : "l"(a), "l"(b));
}
__device__ __forceinline__ unsigned long long splat2(float x) {
    unsigned long long r;
    asm("mov.b64 %0, {%1, %1};" : "=l"(r) : "r"(__float_as_uint(x)));
    return r;
}
__device__ __forceinline__ float2 unpack2(unsigned long long v) {
    float2 f;
    asm("mov.b64 {%0, %1}, %2;" : "=f"(f.x), "=f"(f.y) : "l"(v));
    return f;
}

// ---------------- zero counters ---------------------------------------------
__global__ void k_zero() {
    int i = blockIdx.x * blockDim.x + threadIdx.x;
    if (i < NP) { c_ppi[i] = 0; c_dti[i] = 0; }
}

// ---------------- bin edges by target node (counts = histogram) -------------
__global__ void k_bin(const int* __restrict__ ei,
                      const int* __restrict__ dd, const int* __restrict__ dp) {
    const int stride = gridDim.x * blockDim.x;
    for (int e = blockIdx.x * blockDim.x + threadIdx.x; e < EP + ED; e += stride) {
        if (e < EP) {
            int row = __ldg(ei + e);
            int col = __ldg(ei + EP + e);
            int s = atomicAdd(&c_ppi[col], 1);
            if (s < CAP_P) bin_ppi[(size_t)col * CAP_P + s] = row;
        } else {
            int i = e - EP;
            int d = __ldg(dd + i);
            int p = __ldg(dp + i);
            int s = atomicAdd(&c_dti[p], 1);
            if (s < CAP_D) bin_dti[(size_t)p * CAP_D + s] = d;
        }
    }
}

// ---------------- dinv + rcnt ------------------------------------------------
__global__ void k_dinv() {
    int i = blockIdx.x * blockDim.x + threadIdx.x;
    if (i < NP) {
        g_dinv[i] = rsqrtf((float)c_ppi[i] + 1.f);   // + self loop
        g_rcnt[i] = 1.f / fmaxf((float)c_dti[i], 1.f);
    }
}

// ---------------- fused protein GEMMs (FFMA2, 128x128 tile, 8x8 micro) ------
// g_xw  = dinv[r] * (x @ W_gcn)           (premultiplied for aggregation)
// g_acc = x @ W_pr + b_pr + b_gcn + 1e-6 + dinv[r] * g_xw[r]   (self loop)
__global__ __launch_bounds__(256, 1) void k_gemm_prot(
    const float* __restrict__ x,
    const float* __restrict__ Wg, const float* __restrict__ Wp,
    const float* __restrict__ bg, const float* __restrict__ bp)
{
    extern __shared__ float sm[];
    float* sWg = sm;                     // 128*128
    float* sWp = sm + DD * DD;           // 128*128
    float* sX  = sm + 2 * DD * DD;       // 128 * XPAD (k-major, padded)
    const int tid  = threadIdx.x;
    const int row0 = blockIdx.x * 128;

    for (int idx = tid; idx < DD * DD / 4; idx += 256) {
        reinterpret_cast<float4*>(sWg)[idx] = __ldg(reinterpret_cast<const float4*>(Wg) + idx);
        reinterpret_cast<float4*>(sWp)[idx] = __ldg(reinterpret_cast<const float4*>(Wp) + idx);
    }
    for (int idx = tid; idx < 128 * DD; idx += 256) {
        int r = idx >> 7, c = idx & 127;
        int gr = row0 + r;
        sX[c * XPAD + r] = (gr < NP) ? __ldg(x + (size_t)gr * DD + c) : 0.f;
    }
    __syncthreads();

    const int c0 = (tid & 15) * 8;
    const int r0 = (tid >> 4) * 8;
    unsigned long long aG[8][4], aP[8][4];
#pragma unroll
    for (int i = 0; i < 8; i++)
#pragma unroll
        for (int j = 0; j < 4; j++) { aG[i][j] = 0ull; aP[i][j] = 0ull; }

#pragma unroll 4
    for (int k = 0; k < DD; k++) {
        float4 alo = *reinterpret_cast<const float4*>(sX + k * XPAD + r0);
        float4 ahi = *reinterpret_cast<const float4*>(sX + k * XPAD + r0 + 4);
        ulonglong2 bg0 = *reinterpret_cast<const ulonglong2*>(sWg + k * DD + c0);
        ulonglong2 bg1 = *reinterpret_cast<const ulonglong2*>(sWg + k * DD + c0 + 4);
        ulonglong2 bp0 = *reinterpret_cast<const ulonglong2*>(sWp + k * DD + c0);
        ulonglong2 bp1 = *reinterpret_cast<const ulonglong2*>(sWp + k * DD + c0 + 4);
        float ar[8] = {alo.x, alo.y, alo.z, alo.w, ahi.x, ahi.y, ahi.z, ahi.w};
#pragma unroll
        for (int i = 0; i < 8; i++) {
            unsigned long long a2 = splat2(ar[i]);
            fma2(aG[i][0], a2, bg0.x); fma2(aG[i][1], a2, bg0.y);
            fma2(aG[i][2], a2, bg1.x); fma2(aG[i][3], a2, bg1.y);
            fma2(aP[i][0], a2, bp0.x); fma2(aP[i][1], a2, bp0.y);
            fma2(aP[i][2], a2, bp1.x); fma2(aP[i][3], a2, bp1.y);
        }
    }

    float4 bgA = __ldg(reinterpret_cast<const float4*>(bg + c0));
    float4 bgB = __ldg(reinterpret_cast<const float4*>(bg + c0 + 4));
    float4 bpA = __ldg(reinterpret_cast<const float4*>(bp + c0));
    float4 bpB = __ldg(reinterpret_cast<const float4*>(bp + c0 + 4));
    float bias[8] = {bgA.x + bpA.x + 1e-6f, bgA.y + bpA.y + 1e-6f,
                     bgA.z + bpA.z + 1e-6f, bgA.w + bpA.w + 1e-6f,
                     bgB.x + bpB.x + 1e-6f, bgB.y + bpB.y + 1e-6f,
                     bgB.z + bpB.z + 1e-6f, bgB.w + bpB.w + 1e-6f};
#pragma unroll
    for (int i = 0; i < 8; i++) {
        int gr = row0 + r0 + i;
        if (gr < NP) {
            float di = g_dinv[gr];
            float xs[8], oa[8];
#pragma unroll
            for (int j = 0; j < 4; j++) {
                float2 fg = unpack2(aG[i][j]);
                float2 fp = unpack2(aP[i][j]);
                xs[2*j]   = di * fg.x;                          // premultiplied
                xs[2*j+1] = di * fg.y;
                oa[2*j]   = fp.x + bias[2*j]   + di * xs[2*j];  // = di^2 * xw
                oa[2*j+1] = fp.y + bias[2*j+1] + di * xs[2*j+1];
            }
            float* pw = g_xw  + (size_t)gr * DD + c0;
            float* pa = g_acc + (size_t)gr * DD + c0;
            *reinterpret_cast<float4*>(pw)     = make_float4(xs[0], xs[1], xs[2], xs[3]);
            *reinterpret_cast<float4*>(pw + 4) = make_float4(xs[4], xs[5], xs[6], xs[7]);
            *reinterpret_cast<float4*>(pa)     = make_float4(oa[0], oa[1], oa[2], oa[3]);
            *reinterpret_cast<float4*>(pa + 4) = make_float4(oa[4], oa[5], oa[6], oa[7]);
        }
    }
}

// ---------------- drug GEMM: g_yd = x_drug @ W_td + b_td (FFMA2) ------------
__global__ __launch_bounds__(256, 1) void k_gemm_drug(
    const float* __restrict__ x, const float* __restrict__ W,
    const float* __restrict__ b)
{
    extern __shared__ float sm[];
    float* sW = sm;                  // 128*128
    float* sX = sm + DD * DD;        // 128*XPAD
    const int tid  = threadIdx.x;
    const int row0 = blockIdx.x * 128;

    for (int idx = tid; idx < DD * DD / 4; idx += 256)
        reinterpret_cast<float4*>(sW)[idx] = __ldg(reinterpret_cast<const float4*>(W) + idx);
    for (int idx = tid; idx < 128 * DD; idx += 256) {
        int r = idx >> 7, c = idx & 127;
        int gr = row0 + r;
        sX[c * XPAD + r] = (gr < ND) ? __ldg(x + (size_t)gr * DD + c) : 0.f;
    }
    __syncthreads();

    const int c0 = (tid & 15) * 8;
    const int r0 = (tid >> 4) * 8;
    unsigned long long acc[8][4];
#pragma unroll
    for (int i = 0; i < 8; i++)
#pragma unroll
        for (int j = 0; j < 4; j++) acc[i][j] = 0ull;

#pragma unroll 4
    for (int k = 0; k < DD; k++) {
        float4 alo = *reinterpret_cast<const float4*>(sX + k * XPAD + r0);
        float4 ahi = *reinterpret_cast<const float4*>(sX + k * XPAD + r0 + 4);
        ulonglong2 b0 = *reinterpret_cast<const ulonglong2*>(sW + k * DD + c0);
        ulonglong2 b1 = *reinterpret_cast<const ulonglong2*>(sW + k * DD + c0 + 4);
        float ar[8] = {alo.x, alo.y, alo.z, alo.w, ahi.x, ahi.y, ahi.z, ahi.w};
#pragma unroll
        for (int i = 0; i < 8; i++) {
            unsigned long long a2 = splat2(ar[i]);
            fma2(acc[i][0], a2, b0.x); fma2(acc[i][1], a2, b0.y);
            fma2(acc[i][2], a2, b1.x); fma2(acc[i][3], a2, b1.y);
        }
    }

    float4 bA = __ldg(reinterpret_cast<const float4*>(b + c0));
    float4 bB = __ldg(reinterpret_cast<const float4*>(b + c0 + 4));
    float bias[8] = {bA.x, bA.y, bA.z, bA.w, bB.x, bB.y, bB.z, bB.w};
#pragma unroll
    for (int i = 0; i < 8; i++) {
        int gr = row0 + r0 + i;
        if (gr < ND) {
            float o[8];
#pragma unroll
            for (int j = 0; j < 4; j++) {
                float2 f = unpack2(acc[i][j]);
                o[2*j] = f.x + bias[2*j]; o[2*j+1] = f.y + bias[2*j+1];
            }
            float* py = g_yd + (size_t)gr * DD + c0;
            *reinterpret_cast<float4*>(py)     = make_float4(o[0], o[1], o[2], o[3]);
            *reinterpret_cast<float4*>(py + 4) = make_float4(o[4], o[5], o[6], o[7]);
        }
    }
}

// ---------------- fused gather-aggregate + LayerNorm: warp per node ---------
// v = g_acc[n] + dinv[n] * sum_{src in bin_ppi[n]} g_xw[src]
//             + rcnt[n] * sum_{d in bin_dti[n]}  g_yd[d]
// out[n] = LN(v)
__global__ void k_agg(float* __restrict__ out) {
    size_t t = (size_t)blockIdx.x * blockDim.x + threadIdx.x;
    int n = (int)(t >> 5);
    if (n >= NP) return;
    int lane = (int)(t & 31);
    const int off = lane * 4;

    float4 v = *reinterpret_cast<const float4*>(g_acc + (size_t)n * DD + off);

    // PPI aggregation (g_xw rows are premultiplied by dinv[src])
    int cp = min(c_ppi[n], CAP_P);
    float4 s = make_float4(0.f, 0.f, 0.f, 0.f);
    const int* lp = bin_ppi + (size_t)n * CAP_P;
#pragma unroll 4
    for (int j = 0; j < cp; j++) {
        int src = __ldg(lp + j);
        float4 g = *reinterpret_cast<const float4*>(g_xw + (size_t)src * DD + off);
        s.x += g.x; s.y += g.y; s.z += g.z; s.w += g.w;
    }
    float di = g_dinv[n];
    v.x += di * s.x; v.y += di * s.y; v.z += di * s.z; v.w += di * s.w;

    // DTI aggregation
    int cd = min(c_dti[n], CAP_D);
    float4 u = make_float4(0.f, 0.f, 0.f, 0.f);
    const int* ld = bin_dti + (size_t)n * CAP_D;
#pragma unroll 4
    for (int j = 0; j < cd; j++) {
        int d = __ldg(ld + j);
        float4 g = *reinterpret_cast<const float4*>(g_yd + (size_t)d * DD + off);
        u.x += g.x; u.y += g.y; u.z += g.z; u.w += g.w;
    }
    float rc = g_rcnt[n];
    v.x += rc * u.x; v.y += rc * u.y; v.z += rc * u.z; v.w += rc * u.w;

    // LayerNorm across the 128 features (warp reduction)
    float sum = v.x + v.y + v.z + v.w;
#pragma unroll
    for (int o = 16; o > 0; o >>= 1) sum += __shfl_xor_sync(0xFFFFFFFFu, sum, o);
    float mu = sum * (1.f / DD);
    float4 d4 = make_float4(v.x - mu, v.y - mu, v.z - mu, v.w - mu);
    float ss = d4.x * d4.x + d4.y * d4.y + d4.z * d4.z + d4.w * d4.w;
#pragma unroll
    for (int o = 16; o > 0; o >>= 1) ss += __shfl_xor_sync(0xFFFFFFFFu, ss, o);
    float inv = rsqrtf(ss * (1.f / DD) + LN_EPS);
    float4 r4 = make_float4(d4.x * inv, d4.y * inv, d4.z * inv, d4.w * inv);
    *reinterpret_cast<float4*>(out + (size_t)n * DD + off) = r4;
}

// ---------------- launch ----------------------------------------------------
extern "C" void kernel_launch(void* const* d_in, const int* in_sizes, int n_in,
                              void* d_out, int out_size) {
    const float* x_prot = (const float*)d_in[0];
    const float* x_drug = (const float*)d_in[1];
    const float* W_gcn  = (const float*)d_in[2];
    const float* b_gcn  = (const float*)d_in[3];
    const float* W_td   = (const float*)d_in[4];
    const float* b_td   = (const float*)d_in[5];
    const float* W_pr   = (const float*)d_in[6];
    const float* b_pr   = (const float*)d_in[7];
    const int*   ppi    = (const int*)d_in[8];   // [2, EP] flattened
    const int*   dti_d  = (const int*)d_in[9];
    const int*   dti_p  = (const int*)d_in[10];
    float* out = (float*)d_out;

    const int SMEM_PROT = (2 * DD * DD + DD * XPAD) * 4;  // 198656 B
    const int SMEM_DRUG = (DD * DD + DD * XPAD) * 4;      // 133120 B
    cudaFuncSetAttribute(k_gemm_prot, cudaFuncAttributeMaxDynamicSharedMemorySize, SMEM_PROT);
    cudaFuncSetAttribute(k_gemm_drug, cudaFuncAttributeMaxDynamicSharedMemorySize, SMEM_DRUG);

    // 1. zero counters
    k_zero<<<(NP + 255) / 256, 256>>>();
    // 2. bin all edges by target node (counts become deg/cnt)
    k_bin<<<1184, 256>>>(ppi, dti_d, dti_p);
    // 3. dinv + rcnt
    k_dinv<<<(NP + 255) / 256, 256>>>();
    // 4. fused protein GEMMs  (profiled slot)
    k_gemm_prot<<<(NP + 127) / 128, 256, SMEM_PROT>>>(x_prot, W_gcn, W_pr, b_gcn, b_pr);
    // 5. drug GEMM
    k_gemm_drug<<<(ND + 127) / 128, 256, SMEM_DRUG>>>(x_drug, W_td, b_td);
    // 6. gather-aggregate + LayerNorm (warp per node)
    k_agg<<<(int)(((size_t)NP * 32 + 255) / 256), 256>>>(out);
}

// round 14
// speedup vs baseline: 1.4661x; 1.0295x over previous
#include <cuda_runtime.h>
#include <math.h>

#define NP 100000
#define ND 20000
#define DD 128
#define EP 1600000
#define ED 800000
#define LN_EPS 1e-5f
#define XPAD 132     // sX row stride for 128-row tiles (mult of 4, 4-bank skew)
#define XP256 260    // sX row stride for 256-row tiles (>=256, mult of 4, 4-bank skew)
#define CAP_P 96     // per-node PPI bucket capacity (in-deg ~ Poisson(16))
#define CAP_D 48     // per-node DTI bucket capacity (in-deg ~ Poisson(8))

// ---------------- scratch (static device globals; no runtime allocation) ----
__device__ float g_xw  [(size_t)NP * DD];  // dinv[r] * (x_prot @ W_gcn)  (premultiplied)
__device__ float g_acc [(size_t)NP * DD];  // x@Wpr + b_pr + b_gcn + 1e-6
__device__ float g_yd  [(size_t)ND * DD];  // x_drug @ W_td + b_td
__device__ float g_dinv[NP];
__device__ float g_rcnt[NP];
__device__ int   c_ppi [NP];               // PPI in-degree (excl self loop)
__device__ int   c_dti [NP];               // DTI count per protein
__device__ int   bin_ppi[(size_t)NP * CAP_P];  // src protein ids grouped by target
__device__ int   bin_dti[(size_t)NP * CAP_D];  // drug ids grouped by protein

// ---------------- f32x2 packed math -----------------------------------------
__device__ __forceinline__ void fma2(unsigned long long& d, unsigned long long a,
                                     unsigned long long b) {
    asm("fma.rn.f32x2 %0, %1, %2, %0;" : "+l"(d) : "l"(a), "l"(b));
}
__device__ __forceinline__ unsigned long long splat2(float x) {
    unsigned long long r;
    asm("mov.b64 %0, {%1, %1};" : "=l"(r) : "r"(__float_as_uint(x)));
    return r;
}
__device__ __forceinline__ float2 unpack2(unsigned long long v) {
    float2 f;
    asm("mov.b64 {%0, %1}, %2;" : "=f"(f.x), "=f"(f.y) : "l"(v));
    return f;
}

// ---------------- zero counters ---------------------------------------------
__global__ void k_zero() {
    int i = blockIdx.x * blockDim.x + threadIdx.x;
    if (i < NP) { c_ppi[i] = 0; c_dti[i] = 0; }
}

// ---------------- bin edges by target node (counts = histogram) -------------
__global__ void k_bin(const int* __restrict__ ei,
                      const int* __restrict__ dd, const int* __restrict__ dp) {
    const int stride = gridDim.x * blockDim.x;
    for (int e = blockIdx.x * blockDim.x + threadIdx.x; e < EP + ED; e += stride) {
        if (e < EP) {
            int row = __ldg(ei + e);
            int col = __ldg(ei + EP + e);
            int s = atomicAdd(&c_ppi[col], 1);
            if (s < CAP_P) bin_ppi[(size_t)col * CAP_P + s] = row;
        } else {
            int i = e - EP;
            int d = __ldg(dd + i);
            int p = __ldg(dp + i);
            int s = atomicAdd(&c_dti[p], 1);
            if (s < CAP_D) bin_dti[(size_t)p * CAP_D + s] = d;
        }
    }
}

// ---------------- dinv + rcnt ------------------------------------------------
__global__ void k_dinv() {
    int i = blockIdx.x * blockDim.x + threadIdx.x;
    if (i < NP) {
        g_dinv[i] = rsqrtf((float)c_ppi[i] + 1.f);   // + self loop
        g_rcnt[i] = 1.f / fmaxf((float)c_dti[i], 1.f);
    }
}

// ---------------- single-matrix prot GEMM #1: g_acc = x@Wp + bias -----------
// 512 threads, 256-row tile, 8x8 micro-tile, 16 warps/SM for latency hiding.
__global__ __launch_bounds__(512, 1) void k_gemm_pr(
    const float* __restrict__ x, const float* __restrict__ W,
    const float* __restrict__ bg, const float* __restrict__ bp)
{
    extern __shared__ float sm[];
    float* sW = sm;                  // 128*128
    float* sX = sm + DD * DD;        // 128 k-planes * XP256 rows
    const int tid  = threadIdx.x;
    const int row0 = blockIdx.x * 256;

    for (int idx = tid; idx < DD * DD / 4; idx += 512)
        reinterpret_cast<float4*>(sW)[idx] = __ldg(reinterpret_cast<const float4*>(W) + idx);
    for (int idx = tid; idx < 256 * DD; idx += 512) {
        int r = idx >> 7, c = idx & 127;
        int gr = row0 + r;
        sX[c * XP256 + r] = (gr < NP) ? __ldg(x + (size_t)gr * DD + c) : 0.f;
    }
    __syncthreads();

    const int c0 = (tid & 15) * 8;
    const int r0 = (tid >> 4) * 8;
    unsigned long long acc[8][4];
#pragma unroll
    for (int i = 0; i < 8; i++)
#pragma unroll
        for (int j = 0; j < 4; j++) acc[i][j] = 0ull;

#pragma unroll 4
    for (int k = 0; k < DD; k++) {
        float4 alo = *reinterpret_cast<const float4*>(sX + k * XP256 + r0);
        float4 ahi = *reinterpret_cast<const float4*>(sX + k * XP256 + r0 + 4);
        ulonglong2 b0 = *reinterpret_cast<const ulonglong2*>(sW + k * DD + c0);
        ulonglong2 b1 = *reinterpret_cast<const ulonglong2*>(sW + k * DD + c0 + 4);
        float ar[8] = {alo.x, alo.y, alo.z, alo.w, ahi.x, ahi.y, ahi.z, ahi.w};
#pragma unroll
        for (int i = 0; i < 8; i++) {
            unsigned long long a2 = splat2(ar[i]);
            fma2(acc[i][0], a2, b0.x); fma2(acc[i][1], a2, b0.y);
            fma2(acc[i][2], a2, b1.x); fma2(acc[i][3], a2, b1.y);
        }
    }

    float4 bgA = __ldg(reinterpret_cast<const float4*>(bg + c0));
    float4 bgB = __ldg(reinterpret_cast<const float4*>(bg + c0 + 4));
    float4 bpA = __ldg(reinterpret_cast<const float4*>(bp + c0));
    float4 bpB = __ldg(reinterpret_cast<const float4*>(bp + c0 + 4));
    float bias[8] = {bgA.x + bpA.x + 1e-6f, bgA.y + bpA.y + 1e-6f,
                     bgA.z + bpA.z + 1e-6f, bgA.w + bpA.w + 1e-6f,
                     bgB.x + bpB.x + 1e-6f, bgB.y + bpB.y + 1e-6f,
                     bgB.z + bpB.z + 1e-6f, bgB.w + bpB.w + 1e-6f};
#pragma unroll
    for (int i = 0; i < 8; i++) {
        int gr = row0 + r0 + i;
        if (gr < NP) {
            float o[8];
#pragma unroll
            for (int j = 0; j < 4; j++) {
                float2 f = unpack2(acc[i][j]);
                o[2*j] = f.x + bias[2*j]; o[2*j+1] = f.y + bias[2*j+1];
            }
            float* pa = g_acc + (size_t)gr * DD + c0;
            *reinterpret_cast<float4*>(pa)     = make_float4(o[0], o[1], o[2], o[3]);
            *reinterpret_cast<float4*>(pa + 4) = make_float4(o[4], o[5], o[6], o[7]);
        }
    }
}

// ---------------- single-matrix prot GEMM #2: g_xw = dinv[r]*(x@Wg) ---------
__global__ __launch_bounds__(512, 1) void k_gemm_xw(
    const float* __restrict__ x, const float* __restrict__ W)
{
    extern __shared__ float sm[];
    float* sW = sm;                  // 128*128
    float* sX = sm + DD * DD;        // 128 k-planes * XP256 rows
    const int tid  = threadIdx.x;
    const int row0 = blockIdx.x * 256;

    for (int idx = tid; idx < DD * DD / 4; idx += 512)
        reinterpret_cast<float4*>(sW)[idx] = __ldg(reinterpret_cast<const float4*>(W) + idx);
    for (int idx = tid; idx < 256 * DD; idx += 512) {
        int r = idx >> 7, c = idx & 127;
        int gr = row0 + r;
        sX[c * XP256 + r] = (gr < NP) ? __ldg(x + (size_t)gr * DD + c) : 0.f;
    }
    __syncthreads();

    const int c0 = (tid & 15) * 8;
    const int r0 = (tid >> 4) * 8;
    unsigned long long acc[8][4];
#pragma unroll
    for (int i = 0; i < 8; i++)
#pragma unroll
        for (int j = 0; j < 4; j++) acc[i][j] = 0ull;

#pragma unroll 4
    for (int k = 0; k < DD; k++) {
        float4 alo = *reinterpret_cast<const float4*>(sX + k * XP256 + r0);
        float4 ahi = *reinterpret_cast<const float4*>(sX + k * XP256 + r0 + 4);
        ulonglong2 b0 = *reinterpret_cast<const ulonglong2*>(sW + k * DD + c0);
        ulonglong2 b1 = *reinterpret_cast<const ulonglong2*>(sW + k * DD + c0 + 4);
        float ar[8] = {alo.x, alo.y, alo.z, alo.w, ahi.x, ahi.y, ahi.z, ahi.w};
#pragma unroll
        for (int i = 0; i < 8; i++) {
            unsigned long long a2 = splat2(ar[i]);
            fma2(acc[i][0], a2, b0.x); fma2(acc[i][1], a2, b0.y);
            fma2(acc[i][2], a2, b1.x); fma2(acc[i][3], a2, b1.y);
        }
    }

#pragma unroll
    for (int i = 0; i < 8; i++) {
        int gr = row0 + r0 + i;
        if (gr < NP) {
            float di = g_dinv[gr];
            float o[8];
#pragma unroll
            for (int j = 0; j < 4; j++) {
                float2 f = unpack2(acc[i][j]);
                o[2*j] = di * f.x; o[2*j+1] = di * f.y;   // premultiplied
            }
            float* pw = g_xw + (size_t)gr * DD + c0;
            *reinterpret_cast<float4*>(pw)     = make_float4(o[0], o[1], o[2], o[3]);
            *reinterpret_cast<float4*>(pw + 4) = make_float4(o[4], o[5], o[6], o[7]);
        }
    }
}

// ---------------- drug GEMM: g_yd = x_drug @ W_td + b_td (FFMA2) ------------
__global__ __launch_bounds__(256, 1) void k_gemm_drug(
    const float* __restrict__ x, const float* __restrict__ W,
    const float* __restrict__ b)
{
    extern __shared__ float sm[];
    float* sW = sm;                  // 128*128
    float* sX = sm + DD * DD;        // 128*XPAD
    const int tid  = threadIdx.x;
    const int row0 = blockIdx.x * 128;

    for (int idx = tid; idx < DD * DD / 4; idx += 256)
        reinterpret_cast<float4*>(sW)[idx] = __ldg(reinterpret_cast<const float4*>(W) + idx);
    for (int idx = tid; idx < 128 * DD; idx += 256) {
        int r = idx >> 7, c = idx & 127;
        int gr = row0 + r;
        sX[c * XPAD + r] = (gr < ND) ? __ldg(x + (size_t)gr * DD + c) : 0.f;
    }
    __syncthreads();

    const int c0 = (tid & 15) * 8;
    const int r0 = (tid >> 4) * 8;
    unsigned long long acc[8][4];
#pragma unroll
    for (int i = 0; i < 8; i++)
#pragma unroll
        for (int j = 0; j < 4; j++) acc[i][j] = 0ull;

#pragma unroll 4
    for (int k = 0; k < DD; k++) {
        float4 alo = *reinterpret_cast<const float4*>(sX + k * XPAD + r0);
        float4 ahi = *reinterpret_cast<const float4*>(sX + k * XPAD + r0 + 4);
        ulonglong2 b0 = *reinterpret_cast<const ulonglong2*>(sW + k * DD + c0);
        ulonglong2 b1 = *reinterpret_cast<const ulonglong2*>(sW + k * DD + c0 + 4);
        float ar[8] = {alo.x, alo.y, alo.z, alo.w, ahi.x, ahi.y, ahi.z, ahi.w};
#pragma unroll
        for (int i = 0; i < 8; i++) {
            unsigned long long a2 = splat2(ar[i]);
            fma2(acc[i][0], a2, b0.x); fma2(acc[i][1], a2, b0.y);
            fma2(acc[i][2], a2, b1.x); fma2(acc[i][3], a2, b1.y);
        }
    }

    float4 bA = __ldg(reinterpret_cast<const float4*>(b + c0));
    float4 bB = __ldg(reinterpret_cast<const float4*>(b + c0 + 4));
    float bias[8] = {bA.x, bA.y, bA.z, bA.w, bB.x, bB.y, bB.z, bB.w};
#pragma unroll
    for (int i = 0; i < 8; i++) {
        int gr = row0 + r0 + i;
        if (gr < ND) {
            float o[8];
#pragma unroll
            for (int j = 0; j < 4; j++) {
                float2 f = unpack2(acc[i][j]);
                o[2*j] = f.x + bias[2*j]; o[2*j+1] = f.y + bias[2*j+1];
            }
            float* py = g_yd + (size_t)gr * DD + c0;
            *reinterpret_cast<float4*>(py)     = make_float4(o[0], o[1], o[2], o[3]);
            *reinterpret_cast<float4*>(py + 4) = make_float4(o[4], o[5], o[6], o[7]);
        }
    }
}

// ---------------- fused gather-aggregate + LayerNorm: warp per node ---------
// v = g_acc[n] + dinv[n] * (g_xw[n] + sum_{src} g_xw[src])   <- self loop seeded
//             + rcnt[n] * sum_{d} g_yd[d]
// out[n] = LN(v)
__global__ void k_agg(float* __restrict__ out) {
    size_t t = (size_t)blockIdx.x * blockDim.x + threadIdx.x;
    int n = (int)(t >> 5);
    if (n >= NP) return;
    int lane = (int)(t & 31);
    const int off = lane * 4;

    float4 v = *reinterpret_cast<const float4*>(g_acc + (size_t)n * DD + off);

    // PPI aggregation, seeded with own row (self loop): rows premultiplied by dinv[src]
    int cp = min(c_ppi[n], CAP_P);
    float4 s = *reinterpret_cast<const float4*>(g_xw + (size_t)n * DD + off);
    const int* lp = bin_ppi + (size_t)n * CAP_P;
#pragma unroll 4
    for (int j = 0; j < cp; j++) {
        int src = __ldg(lp + j);
        float4 g = *reinterpret_cast<const float4*>(g_xw + (size_t)src * DD + off);
        s.x += g.x; s.y += g.y; s.z += g.z; s.w += g.w;
    }
    float di = g_dinv[n];
    v.x += di * s.x; v.y += di * s.y; v.z += di * s.z; v.w += di * s.w;

    // DTI aggregation
    int cd = min(c_dti[n], CAP_D);
    float4 u = make_float4(0.f, 0.f, 0.f, 0.f);
    const int* ld = bin_dti + (size_t)n * CAP_D;
#pragma unroll 4
    for (int j = 0; j < cd; j++) {
        int d = __ldg(ld + j);
        float4 g = *reinterpret_cast<const float4*>(g_yd + (size_t)d * DD + off);
        u.x += g.x; u.y += g.y; u.z += g.z; u.w += g.w;
    }
    float rc = g_rcnt[n];
    v.x += rc * u.x; v.y += rc * u.y; v.z += rc * u.z; v.w += rc * u.w;

    // LayerNorm across the 128 features (warp reduction)
    float sum = v.x + v.y + v.z + v.w;
#pragma unroll
    for (int o = 16; o > 0; o >>= 1) sum += __shfl_xor_sync(0xFFFFFFFFu, sum, o);
    float mu = sum * (1.f / DD);
    float4 d4 = make_float4(v.x - mu, v.y - mu, v.z - mu, v.w - mu);
    float ss = d4.x * d4.x + d4.y * d4.y + d4.z * d4.z + d4.w * d4.w;
#pragma unroll
    for (int o = 16; o > 0; o >>= 1) ss += __shfl_xor_sync(0xFFFFFFFFu, ss, o);
    float inv = rsqrtf(ss * (1.f / DD) + LN_EPS);
    float4 r4 = make_float4(d4.x * inv, d4.y * inv, d4.z * inv, d4.w * inv);
    *reinterpret_cast<float4*>(out + (size_t)n * DD + off) = r4;
}

// ---------------- launch ----------------------------------------------------
extern "C" void kernel_launch(void* const* d_in, const int* in_sizes, int n_in,
                              void* d_out, int out_size) {
    const float* x_prot = (const float*)d_in[0];
    const float* x_drug = (const float*)d_in[1];
    const float* W_gcn  = (const float*)d_in[2];
    const float* b_gcn  = (const float*)d_in[3];
    const float* W_td   = (const float*)d_in[4];
    const float* b_td   = (const float*)d_in[5];
    const float* W_pr   = (const float*)d_in[6];
    const float* b_pr   = (const float*)d_in[7];
    const int*   ppi    = (const int*)d_in[8];   // [2, EP] flattened
    const int*   dti_d  = (const int*)d_in[9];
    const int*   dti_p  = (const int*)d_in[10];
    float* out = (float*)d_out;

    const int SMEM_1M   = (DD * DD + DD * XP256) * 4;   // 199680 B
    const int SMEM_DRUG = (DD * DD + DD * XPAD) * 4;    // 133120 B
    cudaFuncSetAttribute(k_gemm_pr,  cudaFuncAttributeMaxDynamicSharedMemorySize, SMEM_1M);
    cudaFuncSetAttribute(k_gemm_xw,  cudaFuncAttributeMaxDynamicSharedMemorySize, SMEM_1M);
    cudaFuncSetAttribute(k_gemm_drug, cudaFuncAttributeMaxDynamicSharedMemorySize, SMEM_DRUG);

    // 1. zero counters
    k_zero<<<(NP + 255) / 256, 256>>>();
    // 2. bin all edges by target node (counts become deg/cnt)
    k_bin<<<1184, 256>>>(ppi, dti_d, dti_p);
    // 3. dinv + rcnt
    k_dinv<<<(NP + 255) / 256, 256>>>();
    // 4. prot GEMM Wp -> g_acc   (profiled slot)
    k_gemm_pr<<<(NP + 255) / 256, 512, SMEM_1M>>>(x_prot, W_pr, b_gcn, b_pr);
    // 5. prot GEMM Wg -> g_xw (premultiplied by dinv)
    k_gemm_xw<<<(NP + 255) / 256, 512, SMEM_1M>>>(x_prot, W_gcn);
    // 6. drug GEMM
    k_gemm_drug<<<(ND + 127) / 128, 256, SMEM_DRUG>>>(x_drug, W_td, b_td);
    // 7. gather-aggregate + LayerNorm (warp per node, self loop seeded)
    k_agg<<<(int)(((size_t)NP * 32 + 255) / 256), 256>>>(out);
}

// round 16
// speedup vs baseline: 1.5111x; 1.0307x over previous
#include <cuda_runtime.h>
#include <cuda_bf16.h>
#include <math.h>
#include <stdint.h>

#define NP 100000
#define ND 20000
#define DD 128
#define EP 1600000
#define ED 800000
#define LN_EPS 1e-5f
#define XPAD 132
#define CAP_P 96
#define CAP_D 48

// ---------------- scratch -----------------------------------------------------
__device__ float g_xw  [(size_t)NP * DD];  // dinv[r] * (x_prot @ W_gcn)
__device__ float g_acc [(size_t)NP * DD];  // x@Wpr + b_pr + b_gcn + 1e-6
__device__ float g_yd  [(size_t)ND * DD];  // x_drug @ W_td + b_td
__device__ float g_dinv[NP];
__device__ float g_rcnt[NP];
__device__ int   c_ppi [NP];
__device__ int   c_dti [NP];
__device__ int   bin_ppi[(size_t)NP * CAP_P];
__device__ int   bin_dti[(size_t)NP * CAP_D];

// ---------------- f32x2 packed math (drug GEMM) ------------------------------
__device__ __forceinline__ void fma2(unsigned long long& d, unsigned long long a,
                                     unsigned long long b) {
    asm("fma.rn.f32x2 %0, %1, %2, %0;" : "+l"(d) : "l"(a), "l"(b));
}
__device__ __forceinline__ unsigned long long splat2(float x) {
    unsigned long long r;
    asm("mov.b64 %0, {%1, %1};" : "=l"(r) : "r"(__float_as_uint(x)));
    return r;
}
__device__ __forceinline__ float2 unpack2(unsigned long long v) {
    float2 f;
    asm("mov.b64 {%0, %1}, %2;" : "=f"(f.x), "=f"(f.y) : "l"(v));
    return f;
}

// ---------------- bf16 split helpers -----------------------------------------
__device__ __forceinline__ uint32_t pack2_raw(__nv_bfloat16 a, __nv_bfloat16 b) {
    uint32_t x = (uint32_t)__bfloat16_as_ushort(a);
    uint32_t y = (uint32_t)__bfloat16_as_ushort(b);
    return x | (y << 16);
}

// ---------------- mma.sync m16n8k16 bf16 (baseline PTX, sm_80+) --------------
__device__ __forceinline__ void mma_bf16(float* c, const uint32_t* a, const uint32_t* b) {
    asm volatile(
        "mma.sync.aligned.m16n8k16.row.col.f32.bf16.bf16.f32 "
        "{%0,%1,%2,%3}, {%4,%5,%6,%7}, {%8,%9}, {%0,%1,%2,%3};"
        : "+f"(c[0]), "+f"(c[1]), "+f"(c[2]), "+f"(c[3])
        : "r"(a[0]), "r"(a[1]), "r"(a[2]), "r"(a[3]), "r"(b[0]), "r"(b[1]));
}

// ---------------- small kernels ----------------------------------------------
__global__ void k_zero() {
    int i = blockIdx.x * blockDim.x + threadIdx.x;
    if (i < NP) { c_ppi[i] = 0; c_dti[i] = 0; }
}
__global__ void k_bin(const int* __restrict__ ei,
                      const int* __restrict__ dd, const int* __restrict__ dp) {
    const int stride = gridDim.x * blockDim.x;
    for (int e = blockIdx.x * blockDim.x + threadIdx.x; e < EP + ED; e += stride) {
        if (e < EP) {
            int row = __ldg(ei + e);
            int col = __ldg(ei + EP + e);
            int s = atomicAdd(&c_ppi[col], 1);
            if (s < CAP_P) bin_ppi[(size_t)col * CAP_P + s] = row;
        } else {
            int i = e - EP;
            int d = __ldg(dd + i);
            int p = __ldg(dp + i);
            int s = atomicAdd(&c_dti[p], 1);
            if (s < CAP_D) bin_dti[(size_t)p * CAP_D + s] = d;
        }
    }
}
__global__ void k_dinv() {
    int i = blockIdx.x * blockDim.x + threadIdx.x;
    if (i < NP) {
        g_dinv[i] = rsqrtf((float)c_ppi[i] + 1.f);
        g_rcnt[i] = 1.f / fmaxf((float)c_dti[i], 1.f);
    }
}

// ---------------- mma.sync bf16x3 protein GEMM -------------------------------
// One matrix per launch. mode 0: g_acc = x@W + (bg+bp+1e-6). mode 1: g_xw = dinv*(x@W).
// CTA: 128 rows x 128 cols; 8 warps each 32x64 (2 m-tiles x 8 n-tiles of m16n8k16).
// 3-term bf16 split: Ahi*Bhi + Ahi*Bmid + Amid*Bhi.
// smem u32-row-stride 66 (132 bf16) to avoid 8-way bank conflicts.
#define RS 66                         // row stride in u32
#define SA_HI  0
#define SA_MID 33792
#define SBT_HI 67584
#define SBT_MID 101376
#define SBIAS  135168
#define SMEM_MMA 135680

__global__ __launch_bounds__(256, 1) void k_mma(
    const float* __restrict__ x, const float* __restrict__ W,
    const float* __restrict__ bg, const float* __restrict__ bp, int mode)
{
    extern __shared__ char smc[];
    uint32_t* sAhi  = reinterpret_cast<uint32_t*>(smc + SA_HI);
    uint32_t* sAmid = reinterpret_cast<uint32_t*>(smc + SA_MID);
    uint32_t* sBhi  = reinterpret_cast<uint32_t*>(smc + SBT_HI);
    uint32_t* sBmid = reinterpret_cast<uint32_t*>(smc + SBT_MID);
    float* sbias = reinterpret_cast<float*>(smc + SBIAS);
    const int tid = threadIdx.x;
    const int row0 = blockIdx.x * 128;

    if (tid < DD) sbias[tid] = __ldg(bg + tid) + __ldg(bp + tid) + 1e-6f;

    // ---- A staging: x rows -> bf16 hi/mid pairs, row-major [r][kp] ----
    for (int idx = tid; idx < 128 * 64; idx += 256) {
        int r = idx >> 6, kp = idx & 63;
        int gr = row0 + r;
        float2 v = (gr < NP)
            ? *reinterpret_cast<const float2*>(x + (size_t)gr * DD + 2 * kp)
            : make_float2(0.f, 0.f);
        __nv_bfloat16 hx = __float2bfloat16_rn(v.x);
        __nv_bfloat16 hy = __float2bfloat16_rn(v.y);
        __nv_bfloat16 mx = __float2bfloat16_rn(v.x - __bfloat162float(hx));
        __nv_bfloat16 my = __float2bfloat16_rn(v.y - __bfloat162float(hy));
        sAhi [r * RS + kp] = pack2_raw(hx, hy);
        sAmid[r * RS + kp] = pack2_raw(mx, my);
    }

    // ---- W staging: W[k][n] (read coalesced) -> W^T bf16 [n][k] hi/mid ----
    {
        __nv_bfloat16* bThi  = reinterpret_cast<__nv_bfloat16*>(smc + SBT_HI);
        __nv_bfloat16* bTmid = reinterpret_cast<__nv_bfloat16*>(smc + SBT_MID);
        for (int idx = tid; idx < 128 * 32; idx += 256) {
            int k = idx >> 5, n4 = (idx & 31) * 4;
            float4 w = __ldg(reinterpret_cast<const float4*>(W + (size_t)k * DD + n4));
            float wv[4] = {w.x, w.y, w.z, w.w};
#pragma unroll
            for (int j = 0; j < 4; j++) {
                __nv_bfloat16 h = __float2bfloat16_rn(wv[j]);
                __nv_bfloat16 m = __float2bfloat16_rn(wv[j] - __bfloat162float(h));
                int n = n4 + j;
                bThi [n * (2 * RS) + k] = h;   // row stride 132 bf16 = 66 u32
                bTmid[n * (2 * RS) + k] = m;
            }
        }
    }
    __syncthreads();

    // ---- MMA mainloop ----
    const int wid = tid >> 5;
    const int lane = tid & 31;
    const int g = lane >> 2;
    const int tig = lane & 3;
    const int wr0 = (wid >> 1) * 32;   // warp row base: 0,32,64,96
    const int wn0 = (wid & 1) * 64;    // warp col base: 0,64

    float acc[2][8][4];
#pragma unroll
    for (int mt = 0; mt < 2; mt++)
#pragma unroll
        for (int nt = 0; nt < 8; nt++)
#pragma unroll
            for (int j = 0; j < 4; j++) acc[mt][nt][j] = 0.f;

#pragma unroll
    for (int term = 0; term < 3; term++) {
        const uint32_t* A = (term < 2) ? sAhi : sAmid;
        const uint32_t* B = (term == 1) ? sBmid : sBhi;
#pragma unroll
        for (int kc = 0; kc < 8; kc++) {
            int kb = kc * 8;
            uint32_t a[2][4];
#pragma unroll
            for (int mt = 0; mt < 2; mt++) {
                int rbase = wr0 + mt * 16;
                a[mt][0] = A[(rbase + g)     * RS + kb + tig];
                a[mt][1] = A[(rbase + g + 8) * RS + kb + tig];
                a[mt][2] = A[(rbase + g)     * RS + kb + tig + 4];
                a[mt][3] = A[(rbase + g + 8) * RS + kb + tig + 4];
            }
            uint32_t b[8][2];
#pragma unroll
            for (int nt = 0; nt < 8; nt++) {
                int nr = wn0 + nt * 8 + g;
                b[nt][0] = B[nr * RS + kb + tig];
                b[nt][1] = B[nr * RS + kb + tig + 4];
            }
#pragma unroll
            for (int mt = 0; mt < 2; mt++)
#pragma unroll
                for (int nt = 0; nt < 8; nt++)
                    mma_bf16(acc[mt][nt], a[mt], b[nt]);
        }
    }

    // ---- epilogue ----
#pragma unroll
    for (int mt = 0; mt < 2; mt++) {
        int r1 = row0 + wr0 + mt * 16 + g;
        int r2 = r1 + 8;
        float s1 = 0.f, s2 = 0.f;
        if (mode) {
            s1 = (r1 < NP) ? g_dinv[r1] : 0.f;
            s2 = (r2 < NP) ? g_dinv[r2] : 0.f;
        }
#pragma unroll
        for (int nt = 0; nt < 8; nt++) {
            int c = wn0 + nt * 8 + 2 * tig;
            if (mode == 0) {
                if (r1 < NP)
                    *reinterpret_cast<float2*>(g_acc + (size_t)r1 * DD + c) =
                        make_float2(acc[mt][nt][0] + sbias[c], acc[mt][nt][1] + sbias[c + 1]);
                if (r2 < NP)
                    *reinterpret_cast<float2*>(g_acc + (size_t)r2 * DD + c) =
                        make_float2(acc[mt][nt][2] + sbias[c], acc[mt][nt][3] + sbias[c + 1]);
            } else {
                if (r1 < NP)
                    *reinterpret_cast<float2*>(g_xw + (size_t)r1 * DD + c) =
                        make_float2(s1 * acc[mt][nt][0], s1 * acc[mt][nt][1]);
                if (r2 < NP)
                    *reinterpret_cast<float2*>(g_xw + (size_t)r2 * DD + c) =
                        make_float2(s2 * acc[mt][nt][2], s2 * acc[mt][nt][3]);
            }
        }
    }
}

// ---------------- drug GEMM (FFMA2, unchanged) -------------------------------
__global__ __launch_bounds__(256, 1) void k_gemm_drug(
    const float* __restrict__ x, const float* __restrict__ W,
    const float* __restrict__ b)
{
    extern __shared__ float sm[];
    float* sW = sm;
    float* sX = sm + DD * DD;
    const int tid  = threadIdx.x;
    const int row0 = blockIdx.x * 128;

    for (int idx = tid; idx < DD * DD / 4; idx += 256)
        reinterpret_cast<float4*>(sW)[idx] = __ldg(reinterpret_cast<const float4*>(W) + idx);
    for (int idx = tid; idx < 128 * DD; idx += 256) {
        int r = idx >> 7, c = idx & 127;
        int gr = row0 + r;
        sX[c * XPAD + r] = (gr < ND) ? __ldg(x + (size_t)gr * DD + c) : 0.f;
    }
    __syncthreads();

    const int c0 = (tid & 15) * 8;
    const int r0 = (tid >> 4) * 8;
    unsigned long long acc[8][4];
#pragma unroll
    for (int i = 0; i < 8; i++)
#pragma unroll
        for (int j = 0; j < 4; j++) acc[i][j] = 0ull;

#pragma unroll 4
    for (int k = 0; k < DD; k++) {
        float4 alo = *reinterpret_cast<const float4*>(sX + k * XPAD + r0);
        float4 ahi = *reinterpret_cast<const float4*>(sX + k * XPAD + r0 + 4);
        ulonglong2 b0 = *reinterpret_cast<const ulonglong2*>(sW + k * DD + c0);
        ulonglong2 b1 = *reinterpret_cast<const ulonglong2*>(sW + k * DD + c0 + 4);
        float ar[8] = {alo.x, alo.y, alo.z, alo.w, ahi.x, ahi.y, ahi.z, ahi.w};
#pragma unroll
        for (int i = 0; i < 8; i++) {
            unsigned long long a2 = splat2(ar[i]);
            fma2(acc[i][0], a2, b0.x); fma2(acc[i][1], a2, b0.y);
            fma2(acc[i][2], a2, b1.x); fma2(acc[i][3], a2, b1.y);
        }
    }

    float4 bA = __ldg(reinterpret_cast<const float4*>(b + c0));
    float4 bB = __ldg(reinterpret_cast<const float4*>(b + c0 + 4));
    float bias[8] = {bA.x, bA.y, bA.z, bA.w, bB.x, bB.y, bB.z, bB.w};
#pragma unroll
    for (int i = 0; i < 8; i++) {
        int gr = row0 + r0 + i;
        if (gr < ND) {
            float o[8];
#pragma unroll
            for (int j = 0; j < 4; j++) {
                float2 f = unpack2(acc[i][j]);
                o[2*j] = f.x + bias[2*j]; o[2*j+1] = f.y + bias[2*j+1];
            }
            float* py = g_yd + (size_t)gr * DD + c0;
            *reinterpret_cast<float4*>(py)     = make_float4(o[0], o[1], o[2], o[3]);
            *reinterpret_cast<float4*>(py + 4) = make_float4(o[4], o[5], o[6], o[7]);
        }
    }
}

// ---------------- gather-aggregate + LayerNorm (unchanged) -------------------
__global__ void k_agg(float* __restrict__ out) {
    size_t t = (size_t)blockIdx.x * blockDim.x + threadIdx.x;
    int n = (int)(t >> 5);
    if (n >= NP) return;
    int lane = (int)(t & 31);
    const int off = lane * 4;

    float4 v = *reinterpret_cast<const float4*>(g_acc + (size_t)n * DD + off);

    int cp = min(c_ppi[n], CAP_P);
    float4 s = *reinterpret_cast<const float4*>(g_xw + (size_t)n * DD + off);
    const int* lp = bin_ppi + (size_t)n * CAP_P;
#pragma unroll 4
    for (int j = 0; j < cp; j++) {
        int src = __ldg(lp + j);
        float4 g = *reinterpret_cast<const float4*>(g_xw + (size_t)src * DD + off);
        s.x += g.x; s.y += g.y; s.z += g.z; s.w += g.w;
    }
    float di = g_dinv[n];
    v.x += di * s.x; v.y += di * s.y; v.z += di * s.z; v.w += di * s.w;

    int cd = min(c_dti[n], CAP_D);
    float4 u = make_float4(0.f, 0.f, 0.f, 0.f);
    const int* ld = bin_dti + (size_t)n * CAP_D;
#pragma unroll 4
    for (int j = 0; j < cd; j++) {
        int d = __ldg(ld + j);
        float4 g = *reinterpret_cast<const float4*>(g_yd + (size_t)d * DD + off);
        u.x += g.x; u.y += g.y; u.z += g.z; u.w += g.w;
    }
    float rc = g_rcnt[n];
    v.x += rc * u.x; v.y += rc * u.y; v.z += rc * u.z; v.w += rc * u.w;

    float sum = v.x + v.y + v.z + v.w;
#pragma unroll
    for (int o = 16; o > 0; o >>= 1) sum += __shfl_xor_sync(0xFFFFFFFFu, sum, o);
    float mu = sum * (1.f / DD);
    float4 d4 = make_float4(v.x - mu, v.y - mu, v.z - mu, v.w - mu);
    float ss = d4.x * d4.x + d4.y * d4.y + d4.z * d4.z + d4.w * d4.w;
#pragma unroll
    for (int o = 16; o > 0; o >>= 1) ss += __shfl_xor_sync(0xFFFFFFFFu, ss, o);
    float inv = rsqrtf(ss * (1.f / DD) + LN_EPS);
    float4 r4 = make_float4(d4.x * inv, d4.y * inv, d4.z * inv, d4.w * inv);
    *reinterpret_cast<float4*>(out + (size_t)n * DD + off) = r4;
}

// ---------------- launch ----------------------------------------------------
extern "C" void kernel_launch(void* const* d_in, const int* in_sizes, int n_in,
                              void* d_out, int out_size) {
    const float* x_prot = (const float*)d_in[0];
    const float* x_drug = (const float*)d_in[1];
    const float* W_gcn  = (const float*)d_in[2];
    const float* b_gcn  = (const float*)d_in[3];
    const float* W_td   = (const float*)d_in[4];
    const float* b_td   = (const float*)d_in[5];
    const float* W_pr   = (const float*)d_in[6];
    const float* b_pr   = (const float*)d_in[7];
    const int*   ppi    = (const int*)d_in[8];
    const int*   dti_d  = (const int*)d_in[9];
    const int*   dti_p  = (const int*)d_in[10];
    float* out = (float*)d_out;

    const int SMEM_DRUG = (DD * DD + DD * XPAD) * 4;
    cudaFuncSetAttribute(k_mma, cudaFuncAttributeMaxDynamicSharedMemorySize, SMEM_MMA);
    cudaFuncSetAttribute(k_gemm_drug, cudaFuncAttributeMaxDynamicSharedMemorySize, SMEM_DRUG);

    // 1. zero counters
    k_zero<<<(NP + 255) / 256, 256>>>();
    // 2. bin edges by target node
    k_bin<<<1184, 256>>>(ppi, dti_d, dti_p);
    // 3. dinv + rcnt
    k_dinv<<<(NP + 255) / 256, 256>>>();
    // 4. mma.sync bf16x3: g_acc = x@Wpr + bias   (profiled slot)
    k_mma<<<(NP + 127) / 128, 256, SMEM_MMA>>>(x_prot, W_pr, b_gcn, b_pr, 0);
    // 5. mma.sync bf16x3: g_xw = dinv * (x@Wgcn)
    k_mma<<<(NP + 127) / 128, 256, SMEM_MMA>>>(x_prot, W_gcn, b_gcn, b_pr, 1);
    // 6. drug GEMM (FFMA2)
    k_gemm_drug<<<(ND + 127) / 128, 256, SMEM_DRUG>>>(x_drug, W_td, b_td);
    // 7. gather-aggregate + LayerNorm
    k_agg<<<(int)(((size_t)NP * 32 + 255) / 256), 256>>>(out);
}